// round 12
// baseline (speedup 1.0000x reference)
#include <cuda_runtime.h>
#include <cuda_bf16.h>
#include <cstdint>
#include <cstddef>

// ---------------- problem constants ----------------
#define BB   4
#define NQ   4096
#define NV   9216
#define EE   768
#define NH   8
#define NP   4
#define HD   96
#define HF   96
#define WF   96

#define BQ   (BB * NQ)   // 16384 query rows
#define BV   (BB * NV)   // 36864 feat rows
#define NCAT 128         // padded N for offset+attn projection

// ---------------- scratch (device globals) ----------------
__device__ __nv_bfloat16  g_qnorm_bf[(size_t)BQ * EE];
__device__ __nv_bfloat16  g_fnorm_bf[(size_t)BV * EE];
__device__ __nv_bfloat16  g_value_bf[(size_t)BV * EE];     // value proj (bf16)
__device__ float          g_raw     [(size_t)BQ * NCAT];
__device__ __nv_bfloat16  g_wv_bf   [(size_t)EE * EE];
__device__ __nv_bfloat16  g_wo_bf   [(size_t)EE * EE];
__device__ __nv_bfloat16  g_wcat_bf [(size_t)EE * NCAT];
__device__ float          g_bcat    [NCAT];
__device__ __nv_bfloat16  g_msda_bf [(size_t)BQ * EE];

// ---------------- PTX helpers ----------------
__device__ __forceinline__ void ldsm4(uint32_t& r0, uint32_t& r1, uint32_t& r2, uint32_t& r3,
                                      uint32_t addr)
{
    asm volatile("ldmatrix.sync.aligned.m8n8.x4.shared.b16 {%0,%1,%2,%3}, [%4];"
                 : "=r"(r0), "=r"(r1), "=r"(r2), "=r"(r3) : "r"(addr));
}
__device__ __forceinline__ void ldsm4t(uint32_t& r0, uint32_t& r1, uint32_t& r2, uint32_t& r3,
                                       uint32_t addr)
{
    asm volatile("ldmatrix.sync.aligned.m8n8.x4.trans.shared.b16 {%0,%1,%2,%3}, [%4];"
                 : "=r"(r0), "=r"(r1), "=r"(r2), "=r"(r3) : "r"(addr));
}
__device__ __forceinline__ void mma16816(float* c, uint32_t a0, uint32_t a1, uint32_t a2,
                                         uint32_t a3, uint32_t b0, uint32_t b1)
{
    asm volatile("mma.sync.aligned.m16n8k16.row.col.f32.bf16.bf16.f32 "
                 "{%0,%1,%2,%3}, {%4,%5,%6,%7}, {%8,%9}, {%0,%1,%2,%3};"
                 : "+f"(c[0]), "+f"(c[1]), "+f"(c[2]), "+f"(c[3])
                 : "r"(a0), "r"(a1), "r"(a2), "r"(a3), "r"(b0), "r"(b1));
}
#define CP_ASYNC16(dst, src) \
    asm volatile("cp.async.cg.shared.global [%0], [%1], 16;" :: "r"(dst), "l"(src))
#define CP_COMMIT() asm volatile("cp.async.commit_group;" ::: "memory")
#define CP_WAIT1()  asm volatile("cp.async.wait_group 1;"  ::: "memory")

// ---------------- kernel: convert weights to bf16 + pack cat weights ----------------
__global__ void cvt_kernel(const float* __restrict__ Wv, const float* __restrict__ Wo,
                           const float* __restrict__ W_off, const float* __restrict__ b_off,
                           const float* __restrict__ W_attn, const float* __restrict__ b_attn)
{
    int idx = blockIdx.x * blockDim.x + threadIdx.x;
    if (idx < EE * EE) {
        g_wv_bf[idx] = __float2bfloat16(Wv[idx]);
        g_wo_bf[idx] = __float2bfloat16(Wo[idx]);
    }
    if (idx < EE * NCAT) {
        int k = idx / NCAT, n = idx % NCAT;
        float v = 0.f;
        if (n < 64)      v = W_off[k * 64 + n];
        else if (n < 96) v = W_attn[k * 32 + (n - 64)];
        g_wcat_bf[idx] = __float2bfloat16(v);
    }
    if (idx < NCAT) {
        float v = 0.f;
        if (idx < 64)      v = b_off[idx];
        else if (idx < 96) v = b_attn[idx - 64];
        g_bcat[idx] = v;
    }
}

// ---------------- kernel: LayerNorm over E=768, vectorized (192 thr, float4) ----------------
__global__ void ln_kernel(const float* __restrict__ x, const float* __restrict__ w,
                          const float* __restrict__ b, __nv_bfloat16* __restrict__ yb)
{
    __shared__ float rs[6], rq[6];
    int row = blockIdx.x;
    int t = threadIdx.x;                      // 192 threads, 4 floats each
    const float4 v = *(const float4*)(x + (size_t)row * EE + t * 4);
    float s = v.x + v.y + v.z + v.w;
    float q = v.x * v.x + v.y * v.y + v.z * v.z + v.w * v.w;
#pragma unroll
    for (int o = 16; o > 0; o >>= 1) {
        s += __shfl_down_sync(0xffffffffu, s, o);
        q += __shfl_down_sync(0xffffffffu, q, o);
    }
    int wid = t >> 5, lane = t & 31;
    if (lane == 0) { rs[wid] = s; rq[wid] = q; }
    __syncthreads();
    float S = 0.f, Q = 0.f;
#pragma unroll
    for (int i = 0; i < 6; i++) { S += rs[i]; Q += rq[i]; }
    const float inv = 1.0f / (float)EE;
    float mean = S * inv;
    float var  = Q * inv - mean * mean;
    float r    = rsqrtf(var + 1e-6f);
    const float4 wv = *(const float4*)(w + t * 4);
    const float4 bv = *(const float4*)(b + t * 4);
    float o0 = (v.x - mean) * r * wv.x + bv.x;
    float o1 = (v.y - mean) * r * wv.y + bv.y;
    float o2 = (v.z - mean) * r * wv.z + bv.z;
    float o3 = (v.w - mean) * r * wv.w + bv.w;
    __nv_bfloat162 p0 = __floats2bfloat162_rn(o0, o1);
    __nv_bfloat162 p1 = __floats2bfloat162_rn(o2, o3);
    uint2 u = make_uint2(*(uint32_t*)&p0, *(uint32_t*)&p1);
    *(uint2*)&yb[(size_t)row * EE + t * 4] = u;
}

// ---------------- kernel: pipelined bf16 tensor-core GEMM ----------------
// Block tile 128x128, 4 warps (128 thr), warp tile 64x64 (2x2), BK=64,
// 3-stage cp.async, 2 CTAs/SM. Per k-tile: 16 ldmatrix -> 64 MMAs, 1 sync.
// OUT==0: fp32 C = A@B + bias
// OUT==1: bf16 C = A@B + bias
// OUT==2: fp32 C = qin + gamma*(bf16(qnb) + A@B + bias)   (N must equal EE)
template <int OUT>
__global__ void __launch_bounds__(128, 2)
gemm_bf16(const __nv_bfloat16* __restrict__ A, const __nv_bfloat16* __restrict__ Bm,
          const float* __restrict__ bias, void* __restrict__ Cout,
          int M, int N, int K,
          const __nv_bfloat16* __restrict__ qnb, const float* __restrict__ qin,
          const float* __restrict__ gamma)
{
    constexpr int BM = 128, BN = 128, BK = 64, STAGES = 3;
    constexpr int MI = 4;                      // 64/16
    constexpr int NI = 8;                      // 64/8
    constexpr int NJ2 = 4;                     // 64/16 (ldsm4t units)
    constexpr int PA = BK + 8;                 // 72 bf16 (144B pitch, conflict-free)
    constexpr int PB = BN + 8;                 // 136 bf16 (272B pitch)
    constexpr int ASZ = BM * PA * 2;           // 18432
    constexpr int BSZ = BK * PB * 2;           // 17408
    constexpr int SB  = ASZ + BSZ;             // 35840

    extern __shared__ char smem[];
    uint32_t smemU = (uint32_t)__cvta_generic_to_shared(smem);

    int tid = threadIdx.x, warp = tid >> 5, lane = tid & 31;
    int rowBase = blockIdx.y * BM;
    int colBase = blockIdx.x * BN;
    int wm = (warp >> 1) * 64;
    int wn = (warp & 1) * 64;

    // cp.async staging coords (128 threads, 16 chunks each)
    int ar = tid >> 3, ac = (tid & 7) * 8;     // A: 16 rows / round, 8 rounds
    int br = tid >> 4, bc = (tid & 15) * 8;    // B: 8 rows / round, 8 rounds
    const __nv_bfloat16* Ag = A  + (size_t)(rowBase + ar) * K + ac;
    const __nv_bfloat16* Bg = Bm + (size_t)br * N + colBase + bc;
    uint32_t aDst = (uint32_t)(ar * PA + ac) * 2;
    uint32_t bDst = (uint32_t)(br * PB + bc) * 2;

    // ldmatrix offsets within a stage
    uint32_t aLd[MI], bLd[NJ2];
#pragma unroll
    for (int i = 0; i < MI; i++)
        aLd[i] = (uint32_t)((wm + i * 16 + (lane & 15)) * PA + (lane >> 4) * 8) * 2;
#pragma unroll
    for (int j = 0; j < NJ2; j++)
        bLd[j] = (uint32_t)((lane & 15) * PB + wn + j * 16 + (lane >> 4) * 8) * 2;

    float acc[MI][NI][4];
#pragma unroll
    for (int i = 0; i < MI; i++)
#pragma unroll
        for (int j = 0; j < NI; j++)
#pragma unroll
            for (int v = 0; v < 4; v++) acc[i][j][v] = 0.f;

    const int KT = K / BK;                     // 12

    auto issue = [&](int kt, int s) {
        uint32_t aB = smemU + s * SB + aDst;
        uint32_t bB = smemU + s * SB + ASZ + bDst;
#pragma unroll
        for (int r = 0; r < 8; r++)
            CP_ASYNC16(aB + r * 16 * PA * 2, Ag + (size_t)(r * 16) * K + kt);
#pragma unroll
        for (int r = 0; r < 8; r++)
            CP_ASYNC16(bB + r * 8 * PB * 2, Bg + (size_t)(kt + r * 8) * N);
        CP_COMMIT();
    };

    // prologue: stages 0..1
#pragma unroll
    for (int s = 0; s < STAGES - 1; s++) issue(s * BK, s);

    for (int t = 0; t < KT; t++) {
        CP_WAIT1();
        __syncthreads();
        int nk = t + STAGES - 1;
        if (nk < KT) issue(nk * BK, nk % STAGES);
        else CP_COMMIT();   // empty group keeps wait count uniform

        uint32_t aB = smemU + (t % STAGES) * SB;
        uint32_t bB = aB + ASZ;
#pragma unroll
        for (int ks = 0; ks < 4; ks++) {       // 4 k16 steps per BK=64 tile
            uint32_t af[MI][4], bf[NJ2][4];
#pragma unroll
            for (int i = 0; i < MI; i++)
                ldsm4(af[i][0], af[i][1], af[i][2], af[i][3], aB + aLd[i] + ks * 32);
#pragma unroll
            for (int j = 0; j < NJ2; j++)
                ldsm4t(bf[j][0], bf[j][1], bf[j][2], bf[j][3],
                       bB + bLd[j] + ks * 16 * PB * 2);
#pragma unroll
            for (int i = 0; i < MI; i++)
#pragma unroll
                for (int j = 0; j < NI; j++)
                    mma16816(acc[i][j], af[i][0], af[i][1], af[i][2], af[i][3],
                             bf[j >> 1][(j & 1) * 2], bf[j >> 1][(j & 1) * 2 + 1]);
        }
    }

    // epilogue
    int g = lane >> 2, tg = lane & 3;
#pragma unroll
    for (int i = 0; i < MI; i++) {
#pragma unroll
        for (int j = 0; j < NI; j++) {
            int row = rowBase + wm + i * 16 + g;
            int col = colBase + wn + j * 8 + tg * 2;
            float b0 = bias[col], b1 = bias[col + 1];
            float v00 = acc[i][j][0] + b0, v01 = acc[i][j][1] + b1;
            float v10 = acc[i][j][2] + b0, v11 = acc[i][j][3] + b1;
            if (OUT == 2) {
                float gc0 = gamma[col], gc1 = gamma[col + 1];
                size_t o0 = (size_t)row * EE + col;
                size_t o1 = (size_t)(row + 8) * EE + col;
                float2 q0 = *(const float2*)&qin[o0];
                float2 q1 = *(const float2*)&qin[o1];
                __nv_bfloat162 n0 = *(const __nv_bfloat162*)&qnb[o0];
                __nv_bfloat162 n1 = *(const __nv_bfloat162*)&qnb[o1];
                v00 = q0.x + gc0 * (__bfloat162float(n0.x) + v00);
                v01 = q0.y + gc1 * (__bfloat162float(n0.y) + v01);
                v10 = q1.x + gc0 * (__bfloat162float(n1.x) + v10);
                v11 = q1.y + gc1 * (__bfloat162float(n1.y) + v11);
            }
            if (OUT == 1) {
                __nv_bfloat16* C = (__nv_bfloat16*)Cout;
                *(__nv_bfloat162*)&C[(size_t)row * N + col] =
                    __floats2bfloat162_rn(v00, v01);
                *(__nv_bfloat162*)&C[(size_t)(row + 8) * N + col] =
                    __floats2bfloat162_rn(v10, v11);
            } else {
                float* C = (float*)Cout;
                *(float2*)&C[(size_t)row * N + col]       = make_float2(v00, v01);
                *(float2*)&C[(size_t)(row + 8) * N + col] = make_float2(v10, v11);
            }
        }
    }
}

// ---------------- kernel: fused softmax + deformable bilinear sampling ----------------
// One warp per (b*NQ+q, head-pair). Half-warp per head: lanes 0-15 -> head 2*hp,
// lanes 16-31 -> head 2*hp+1. Within a half-warp, lanes 0-11 each own 8 channels
// (one uint4 = 8 bf16 per corner row), so each corner is a single coalesced LDG.128.
__global__ void msda_kernel(const float* __restrict__ refp)
{
    int gwarp = (blockIdx.x * blockDim.x + threadIdx.x) >> 5;
    int lane  = threadIdx.x & 31;
    if (gwarp >= BQ * (NH / 2)) return;
    int bq = gwarp >> 2;                 // / (NH/2)
    int hp = gwarp & 3;
    int h  = hp * 2 + (lane >> 4);
    int li = lane & 15;                  // lane within half-warp; active if li < 12
    int b  = bq >> 12;                   // bq / NQ

    const float* raw = g_raw + (size_t)bq * NCAT;
    float rx = refp[bq * 2 + 0];
    float ry = refp[bq * 2 + 1];

    // softmax over the 4 logits for this lane's head
    float lg[NP];
    float m = -1e30f;
#pragma unroll
    for (int p = 0; p < NP; p++) {
        lg[p] = raw[64 + h * 4 + p];
        m = fmaxf(m, lg[p]);
    }
    float sum = 0.f;
#pragma unroll
    for (int p = 0; p < NP; p++) { lg[p] = expf(lg[p] - m); sum += lg[p]; }
    float rinv = 1.0f / sum;

    const __nv_bfloat16* vbase = g_value_bf + (size_t)b * NV * EE + (size_t)h * HD;
    bool active = (li < 12);

    float acc[8];
#pragma unroll
    for (int k = 0; k < 8; k++) acc[k] = 0.f;

#pragma unroll
    for (int p = 0; p < NP; p++) {
        float lx = rx + raw[h * 8 + p * 2 + 0] * (1.0f / (float)WF);
        float ly = ry + raw[h * 8 + p * 2 + 1] * (1.0f / (float)HF);
        float x = lx * (float)WF - 0.5f;
        float y = ly * (float)HF - 0.5f;
        float a = lg[p] * rinv;
        float fx = floorf(x), fy = floorf(y);
        int x0 = (int)fx, y0 = (int)fy;
        float tx = x - fx, ty = y - fy;
        float w00 = (1.f - tx) * (1.f - ty) * a;
        float w01 = tx * (1.f - ty) * a;
        float w10 = (1.f - tx) * ty * a;
        float w11 = tx * ty * a;
#pragma unroll
        for (int c = 0; c < 4; c++) {
            int xi = x0 + (c & 1);
            int yi = y0 + (c >> 1);
            float w = (c == 0) ? w00 : (c == 1) ? w01 : (c == 2) ? w10 : w11;
            if (active && xi >= 0 && xi < WF && yi >= 0 && yi < HF) {
                const uint4 v = *(const uint4*)(vbase + (size_t)(yi * WF + xi) * EE + li * 8);
                const __nv_bfloat162* pv = (const __nv_bfloat162*)&v;
#pragma unroll
                for (int k = 0; k < 4; k++) {
                    float2 f = __bfloat1622float2(pv[k]);
                    acc[2 * k]     += w * f.x;
                    acc[2 * k + 1] += w * f.y;
                }
            }
        }
    }
    if (active) {
        __nv_bfloat162 p0 = __floats2bfloat162_rn(acc[0], acc[1]);
        __nv_bfloat162 p1 = __floats2bfloat162_rn(acc[2], acc[3]);
        __nv_bfloat162 p2 = __floats2bfloat162_rn(acc[4], acc[5]);
        __nv_bfloat162 p3 = __floats2bfloat162_rn(acc[6], acc[7]);
        uint4 u = make_uint4(*(uint32_t*)&p0, *(uint32_t*)&p1,
                             *(uint32_t*)&p2, *(uint32_t*)&p3);
        *(uint4*)(g_msda_bf + (size_t)bq * EE + (size_t)h * HD + li * 8) = u;
    }
}

// ---------------- launch ----------------
extern "C" void kernel_launch(void* const* d_in, const int* in_sizes, int n_in,
                              void* d_out, int out_size)
{
    (void)in_sizes; (void)n_in; (void)out_size;
    const float* query  = (const float*)d_in[0];
    const float* refp   = (const float*)d_in[1];
    const float* feat   = (const float*)d_in[2];
    const float* ln_q_w = (const float*)d_in[5];
    const float* ln_q_b = (const float*)d_in[6];
    const float* ln_f_w = (const float*)d_in[7];
    const float* ln_f_b = (const float*)d_in[8];
    const float* W_value= (const float*)d_in[9];
    const float* b_value= (const float*)d_in[10];
    const float* W_off  = (const float*)d_in[11];
    const float* b_off  = (const float*)d_in[12];
    const float* W_attn = (const float*)d_in[13];
    const float* b_attn = (const float*)d_in[14];
    const float* W_out  = (const float*)d_in[15];
    const float* b_out  = (const float*)d_in[16];
    const float* gamma  = (const float*)d_in[17];
    float* out = (float*)d_out;

    float *raw, *bcat;
    __nv_bfloat16 *qnorm_bf, *fnorm_bf, *value_bf, *wv_bf, *wo_bf, *wcat_bf, *msda_bf;
    cudaGetSymbolAddress((void**)&qnorm_bf, g_qnorm_bf);
    cudaGetSymbolAddress((void**)&fnorm_bf, g_fnorm_bf);
    cudaGetSymbolAddress((void**)&value_bf, g_value_bf);
    cudaGetSymbolAddress((void**)&raw,      g_raw);
    cudaGetSymbolAddress((void**)&wv_bf,    g_wv_bf);
    cudaGetSymbolAddress((void**)&wo_bf,    g_wo_bf);
    cudaGetSymbolAddress((void**)&wcat_bf,  g_wcat_bf);
    cudaGetSymbolAddress((void**)&bcat,     g_bcat);
    cudaGetSymbolAddress((void**)&msda_bf,  g_msda_bf);

    // dyn smem: 3 stages * (128*72 + 64*136) * 2 bytes = 107520
    const int SMEM = 3 * (128 * 72 * 2 + 64 * 136 * 2);
    cudaFuncSetAttribute(gemm_bf16<0>, cudaFuncAttributeMaxDynamicSharedMemorySize, SMEM);
    cudaFuncSetAttribute(gemm_bf16<1>, cudaFuncAttributeMaxDynamicSharedMemorySize, SMEM);
    cudaFuncSetAttribute(gemm_bf16<2>, cudaFuncAttributeMaxDynamicSharedMemorySize, SMEM);

    // 1. weight conversion + packing
    cvt_kernel<<<(EE * EE + 255) / 256, 256>>>(W_value, W_out, W_off, b_off, W_attn, b_attn);

    // 2. LayerNorms (bf16 outputs, vectorized)
    ln_kernel<<<BQ, 192>>>(query, ln_q_w, ln_q_b, qnorm_bf);
    ln_kernel<<<BV, 192>>>(feat,  ln_f_w, ln_f_b, fnorm_bf);

    // 3. value projection: [36864,768] bf16 out
    gemm_bf16<1><<<dim3(EE / 128, BV / 128), 128, SMEM>>>(
        fnorm_bf, wv_bf, b_value, value_bf, BV, EE, EE, nullptr, nullptr, nullptr);

    // 4. offset+attn projection: [16384,128] fp32 out
    gemm_bf16<0><<<dim3(NCAT / 128, BQ / 128), 128, SMEM>>>(
        qnorm_bf, wcat_bf, bcat, raw, BQ, NCAT, EE, nullptr, nullptr, nullptr);

    // 5. fused softmax + deformable sampling: 1 warp per (b,q, head-pair)
    msda_kernel<<<(BQ * (NH / 2) * 32) / 256, 256>>>(refp);

    // 6. out projection + fused residual: d_out = query + gamma*(qnorm + msda@W_out + b_out)
    gemm_bf16<2><<<dim3(EE / 128, BQ / 128), 128, SMEM>>>(
        msda_bf, wo_bf, b_out, out, BQ, EE, EE, qnorm_bf, query, gamma);
}

// round 13
// speedup vs baseline: 1.0704x; 1.0704x over previous
#include <cuda_runtime.h>
#include <cuda_bf16.h>
#include <cstdint>
#include <cstddef>

// ---------------- problem constants ----------------
#define BB   4
#define NQ   4096
#define NV   9216
#define EE   768
#define NH   8
#define NP   4
#define HD   96
#define HF   96
#define WF   96

#define BQ   (BB * NQ)   // 16384 query rows
#define BV   (BB * NV)   // 36864 feat rows
#define NCAT 128         // padded N for offset+attn projection
#define CVTB 512         // cvt helper blocks inside prep kernel

// ---------------- scratch (device globals) ----------------
__device__ __nv_bfloat16  g_qnorm_bf[(size_t)BQ * EE];
__device__ __nv_bfloat16  g_fnorm_bf[(size_t)BV * EE];
__device__ __nv_bfloat16  g_value_bf[(size_t)BV * EE];     // value proj (bf16)
__device__ float          g_raw     [(size_t)BQ * NCAT];
__device__ __nv_bfloat16  g_wv_bf   [(size_t)EE * EE];
__device__ __nv_bfloat16  g_wo_bf   [(size_t)EE * EE];
__device__ __nv_bfloat16  g_wcat_bf [(size_t)EE * NCAT];
__device__ float          g_bcat    [NCAT];
__device__ __nv_bfloat16  g_msda_bf [(size_t)BQ * EE];

// ---------------- PTX helpers ----------------
__device__ __forceinline__ void ldsm4(uint32_t& r0, uint32_t& r1, uint32_t& r2, uint32_t& r3,
                                      uint32_t addr)
{
    asm volatile("ldmatrix.sync.aligned.m8n8.x4.shared.b16 {%0,%1,%2,%3}, [%4];"
                 : "=r"(r0), "=r"(r1), "=r"(r2), "=r"(r3) : "r"(addr));
}
__device__ __forceinline__ void ldsm4t(uint32_t& r0, uint32_t& r1, uint32_t& r2, uint32_t& r3,
                                       uint32_t addr)
{
    asm volatile("ldmatrix.sync.aligned.m8n8.x4.trans.shared.b16 {%0,%1,%2,%3}, [%4];"
                 : "=r"(r0), "=r"(r1), "=r"(r2), "=r"(r3) : "r"(addr));
}
__device__ __forceinline__ void mma16816(float* c, uint32_t a0, uint32_t a1, uint32_t a2,
                                         uint32_t a3, uint32_t b0, uint32_t b1)
{
    asm volatile("mma.sync.aligned.m16n8k16.row.col.f32.bf16.bf16.f32 "
                 "{%0,%1,%2,%3}, {%4,%5,%6,%7}, {%8,%9}, {%0,%1,%2,%3};"
                 : "+f"(c[0]), "+f"(c[1]), "+f"(c[2]), "+f"(c[3])
                 : "r"(a0), "r"(a1), "r"(a2), "r"(a3), "r"(b0), "r"(b1));
}
#define CP_ASYNC16(dst, src) \
    asm volatile("cp.async.cg.shared.global [%0], [%1], 16;" :: "r"(dst), "l"(src))
#define CP_COMMIT() asm volatile("cp.async.commit_group;" ::: "memory")
#define CP_WAIT1()  asm volatile("cp.async.wait_group 1;"  ::: "memory")

// ---------------- device fn: row LayerNorm (192 threads) ----------------
__device__ __forceinline__ void ln_row(const float* __restrict__ x,
                                       const float* __restrict__ w,
                                       const float* __restrict__ b,
                                       __nv_bfloat16* __restrict__ yb, int row)
{
    __shared__ float rs[6], rq[6];
    int t = threadIdx.x;                      // 192 threads, 4 floats each
    const float4 v = *(const float4*)(x + (size_t)row * EE + t * 4);
    float s = v.x + v.y + v.z + v.w;
    float q = v.x * v.x + v.y * v.y + v.z * v.z + v.w * v.w;
#pragma unroll
    for (int o = 16; o > 0; o >>= 1) {
        s += __shfl_down_sync(0xffffffffu, s, o);
        q += __shfl_down_sync(0xffffffffu, q, o);
    }
    int wid = t >> 5, lane = t & 31;
    if (lane == 0) { rs[wid] = s; rq[wid] = q; }
    __syncthreads();
    float S = 0.f, Q = 0.f;
#pragma unroll
    for (int i = 0; i < 6; i++) { S += rs[i]; Q += rq[i]; }
    const float inv = 1.0f / (float)EE;
    float mean = S * inv;
    float var  = Q * inv - mean * mean;
    float r    = rsqrtf(var + 1e-6f);
    const float4 wv = *(const float4*)(w + t * 4);
    const float4 bv = *(const float4*)(b + t * 4);
    float o0 = (v.x - mean) * r * wv.x + bv.x;
    float o1 = (v.y - mean) * r * wv.y + bv.y;
    float o2 = (v.z - mean) * r * wv.z + bv.z;
    float o3 = (v.w - mean) * r * wv.w + bv.w;
    __nv_bfloat162 p0 = __floats2bfloat162_rn(o0, o1);
    __nv_bfloat162 p1 = __floats2bfloat162_rn(o2, o3);
    uint2 u = make_uint2(*(uint32_t*)&p0, *(uint32_t*)&p1);
    *(uint2*)&yb[(size_t)row * EE + t * 4] = u;
}

// ---------------- kernel: fused prep = LN(feat) + LN(query) + weight cvt ----------------
// grid: [0,BV) LN(feat); [BV,BV+BQ) LN(query); rest: weight conversion
__global__ void prep_kernel(const float* __restrict__ query, const float* __restrict__ feat,
                            const float* __restrict__ ln_q_w, const float* __restrict__ ln_q_b,
                            const float* __restrict__ ln_f_w, const float* __restrict__ ln_f_b,
                            const float* __restrict__ Wv, const float* __restrict__ Wo,
                            const float* __restrict__ W_off, const float* __restrict__ b_off,
                            const float* __restrict__ W_attn, const float* __restrict__ b_attn)
{
    int blk = blockIdx.x;
    if (blk < BV) {
        ln_row(feat, ln_f_w, ln_f_b, g_fnorm_bf, blk);
        return;
    }
    blk -= BV;
    if (blk < BQ) {
        ln_row(query, ln_q_w, ln_q_b, g_qnorm_bf, blk);
        return;
    }
    // weight conversion blocks
    int cid = blk - BQ;
    const int STR = CVTB * 192;
    for (size_t i = (size_t)cid * 192 + threadIdx.x; i < (size_t)EE * EE; i += STR) {
        g_wv_bf[i] = __float2bfloat16(Wv[i]);
        g_wo_bf[i] = __float2bfloat16(Wo[i]);
    }
    for (size_t i = (size_t)cid * 192 + threadIdx.x; i < (size_t)EE * NCAT; i += STR) {
        int k = (int)(i / NCAT), n = (int)(i % NCAT);
        float v = 0.f;
        if (n < 64)      v = W_off[k * 64 + n];
        else if (n < 96) v = W_attn[k * 32 + (n - 64)];
        g_wcat_bf[i] = __float2bfloat16(v);
    }
    if (cid == 0 && threadIdx.x < NCAT) {
        int idx = threadIdx.x;
        float v = 0.f;
        if (idx < 64)      v = b_off[idx];
        else if (idx < 96) v = b_attn[idx - 64];
        g_bcat[idx] = v;
    }
}

// ---------------- GEMM mainloop body (R11: BK=32, 4 warps, warp tile 64x64) ----------------
// Computes acc for tile (rowBase, colBase) of C = A[M,K]@B[K,N].
struct GemmCfg {
    static constexpr int BM = 128, BN = 128, BK = 32, STAGES = 3;
    static constexpr int MI = 4, NI = 8, NJ2 = 4;
    static constexpr int PA = BK + 8;                 // 40 bf16
    static constexpr int PB = BN + 8;                 // 136 bf16
    static constexpr int ASZ = BM * PA * 2;
    static constexpr int BSZ = BK * PB * 2;
    static constexpr int SB  = ASZ + BSZ;
};

__device__ __forceinline__ void gemm_mainloop(
    const __nv_bfloat16* __restrict__ A, const __nv_bfloat16* __restrict__ Bm,
    int N, int K, int rowBase, int colBase, uint32_t smemU,
    float acc[GemmCfg::MI][GemmCfg::NI][4])
{
    using C = GemmCfg;
    int tid = threadIdx.x, warp = tid >> 5, lane = tid & 31;
    int wm = (warp >> 1) * 64;
    int wn = (warp & 1) * 64;

    int ar = tid >> 2, ac = (tid & 3) * 8;     // A: 32 rows / round, 4 rounds
    int br = tid >> 4, bc = (tid & 15) * 8;    // B: 8 rows / round, 4 rounds
    const __nv_bfloat16* Ag = A  + (size_t)(rowBase + ar) * K + ac;
    const __nv_bfloat16* Bg = Bm + (size_t)br * N + colBase + bc;
    uint32_t aDst = (uint32_t)(ar * C::PA + ac) * 2;
    uint32_t bDst = (uint32_t)(br * C::PB + bc) * 2;

    uint32_t aLd[C::MI], bLd[C::NJ2];
#pragma unroll
    for (int i = 0; i < C::MI; i++)
        aLd[i] = (uint32_t)((wm + i * 16 + (lane & 15)) * C::PA + (lane >> 4) * 8) * 2;
#pragma unroll
    for (int j = 0; j < C::NJ2; j++)
        bLd[j] = (uint32_t)((lane & 15) * C::PB + wn + j * 16 + (lane >> 4) * 8) * 2;

#pragma unroll
    for (int i = 0; i < C::MI; i++)
#pragma unroll
        for (int j = 0; j < C::NI; j++)
#pragma unroll
            for (int v = 0; v < 4; v++) acc[i][j][v] = 0.f;

    const int KT = K / C::BK;

    auto issue = [&](int kt, int s) {
        uint32_t aB = smemU + s * C::SB + aDst;
        uint32_t bB = smemU + s * C::SB + C::ASZ + bDst;
#pragma unroll
        for (int r = 0; r < 4; r++)
            CP_ASYNC16(aB + r * 32 * C::PA * 2, Ag + (size_t)(r * 32) * K + kt);
#pragma unroll
        for (int r = 0; r < 4; r++)
            CP_ASYNC16(bB + r * 8 * C::PB * 2, Bg + (size_t)(kt + r * 8) * N);
        CP_COMMIT();
    };

#pragma unroll
    for (int s = 0; s < C::STAGES - 1; s++) issue(s * C::BK, s);

    for (int t = 0; t < KT; t++) {
        CP_WAIT1();
        __syncthreads();
        int nk = t + C::STAGES - 1;
        if (nk < KT) issue(nk * C::BK, nk % C::STAGES);
        else CP_COMMIT();

        uint32_t aB = smemU + (t % C::STAGES) * C::SB;
        uint32_t bB = aB + C::ASZ;
#pragma unroll
        for (int ks = 0; ks < 2; ks++) {
            uint32_t af[C::MI][4], bf[C::NJ2][4];
#pragma unroll
            for (int i = 0; i < C::MI; i++)
                ldsm4(af[i][0], af[i][1], af[i][2], af[i][3], aB + aLd[i] + ks * 32);
#pragma unroll
            for (int j = 0; j < C::NJ2; j++)
                ldsm4t(bf[j][0], bf[j][1], bf[j][2], bf[j][3],
                       bB + bLd[j] + ks * 16 * C::PB * 2);
#pragma unroll
            for (int i = 0; i < C::MI; i++)
#pragma unroll
                for (int j = 0; j < C::NI; j++)
                    mma16816(acc[i][j], af[i][0], af[i][1], af[i][2], af[i][3],
                             bf[j >> 1][(j & 1) * 2], bf[j >> 1][(j & 1) * 2 + 1]);
        }
    }
}

// ---------------- kernel: merged value + cat GEMM ----------------
// grid (6, 416): y<288 -> value tiles (bf16 out); y>=288 & x==0 -> cat tiles (f32 out)
__global__ void __launch_bounds__(128, 2)
gemm_vc(const __nv_bfloat16* __restrict__ Av, const __nv_bfloat16* __restrict__ Bv,
        const float* __restrict__ biasv,
        const __nv_bfloat16* __restrict__ Ac, const __nv_bfloat16* __restrict__ Bc,
        const float* __restrict__ biasc)
{
    extern __shared__ char smem[];
    uint32_t smemU = (uint32_t)__cvta_generic_to_shared(smem);

    const __nv_bfloat16 *A, *Bm;
    const float* bias;
    int N, rowBase, colBase, mode;
    if (blockIdx.y < 288) {
        A = Av; Bm = Bv; bias = biasv; N = EE; mode = 1;
        rowBase = blockIdx.y * 128; colBase = blockIdx.x * 128;
    } else {
        if (blockIdx.x != 0) return;
        A = Ac; Bm = Bc; bias = biasc; N = NCAT; mode = 0;
        rowBase = (blockIdx.y - 288) * 128; colBase = 0;
    }

    float acc[GemmCfg::MI][GemmCfg::NI][4];
    gemm_mainloop(A, Bm, N, EE, rowBase, colBase, smemU, acc);

    int lane = threadIdx.x & 31, warp = threadIdx.x >> 5;
    int wm = (warp >> 1) * 64, wn = (warp & 1) * 64;
    int g = lane >> 2, tg = lane & 3;
#pragma unroll
    for (int i = 0; i < GemmCfg::MI; i++) {
#pragma unroll
        for (int j = 0; j < GemmCfg::NI; j++) {
            int row = rowBase + wm + i * 16 + g;
            int col = colBase + wn + j * 8 + tg * 2;
            float b0 = bias[col], b1 = bias[col + 1];
            float v00 = acc[i][j][0] + b0, v01 = acc[i][j][1] + b1;
            float v10 = acc[i][j][2] + b0, v11 = acc[i][j][3] + b1;
            if (mode == 1) {
                *(__nv_bfloat162*)&g_value_bf[(size_t)row * EE + col] =
                    __floats2bfloat162_rn(v00, v01);
                *(__nv_bfloat162*)&g_value_bf[(size_t)(row + 8) * EE + col] =
                    __floats2bfloat162_rn(v10, v11);
            } else {
                *(float2*)&g_raw[(size_t)row * NCAT + col]       = make_float2(v00, v01);
                *(float2*)&g_raw[(size_t)(row + 8) * NCAT + col] = make_float2(v10, v11);
            }
        }
    }
}

// ---------------- kernel: out projection + fused residual ----------------
// fp32 out = qin + gamma*(bf16(qnb) + A@B + bias), N == EE
__global__ void __launch_bounds__(128, 2)
gemm_out(const __nv_bfloat16* __restrict__ A, const __nv_bfloat16* __restrict__ Bm,
         const float* __restrict__ bias, float* __restrict__ Cout,
         const __nv_bfloat16* __restrict__ qnb, const float* __restrict__ qin,
         const float* __restrict__ gamma)
{
    extern __shared__ char smem[];
    uint32_t smemU = (uint32_t)__cvta_generic_to_shared(smem);
    int rowBase = blockIdx.y * 128;
    int colBase = blockIdx.x * 128;

    float acc[GemmCfg::MI][GemmCfg::NI][4];
    gemm_mainloop(A, Bm, EE, EE, rowBase, colBase, smemU, acc);

    int lane = threadIdx.x & 31, warp = threadIdx.x >> 5;
    int wm = (warp >> 1) * 64, wn = (warp & 1) * 64;
    int g = lane >> 2, tg = lane & 3;
#pragma unroll
    for (int i = 0; i < GemmCfg::MI; i++) {
#pragma unroll
        for (int j = 0; j < GemmCfg::NI; j++) {
            int row = rowBase + wm + i * 16 + g;
            int col = colBase + wn + j * 8 + tg * 2;
            float b0 = bias[col], b1 = bias[col + 1];
            float v00 = acc[i][j][0] + b0, v01 = acc[i][j][1] + b1;
            float v10 = acc[i][j][2] + b0, v11 = acc[i][j][3] + b1;
            float gc0 = gamma[col], gc1 = gamma[col + 1];
            size_t o0 = (size_t)row * EE + col;
            size_t o1 = (size_t)(row + 8) * EE + col;
            float2 q0 = *(const float2*)&qin[o0];
            float2 q1 = *(const float2*)&qin[o1];
            __nv_bfloat162 n0 = *(const __nv_bfloat162*)&qnb[o0];
            __nv_bfloat162 n1 = *(const __nv_bfloat162*)&qnb[o1];
            v00 = q0.x + gc0 * (__bfloat162float(n0.x) + v00);
            v01 = q0.y + gc1 * (__bfloat162float(n0.y) + v01);
            v10 = q1.x + gc0 * (__bfloat162float(n1.x) + v10);
            v11 = q1.y + gc1 * (__bfloat162float(n1.y) + v11);
            *(float2*)&Cout[o0] = make_float2(v00, v01);
            *(float2*)&Cout[o1] = make_float2(v10, v11);
        }
    }
}

// ---------------- kernel: fused softmax + deformable bilinear sampling ----------------
__global__ void msda_kernel(const float* __restrict__ refp)
{
    int gwarp = (blockIdx.x * blockDim.x + threadIdx.x) >> 5;
    int lane  = threadIdx.x & 31;
    if (gwarp >= BQ * (NH / 2)) return;
    int bq = gwarp >> 2;                 // / (NH/2)
    int hp = gwarp & 3;
    int h  = hp * 2 + (lane >> 4);
    int li = lane & 15;                  // lane within half-warp; active if li < 12
    int b  = bq >> 12;                   // bq / NQ

    const float* raw = g_raw + (size_t)bq * NCAT;
    float rx = refp[bq * 2 + 0];
    float ry = refp[bq * 2 + 1];

    float lg[NP];
    float m = -1e30f;
#pragma unroll
    for (int p = 0; p < NP; p++) {
        lg[p] = raw[64 + h * 4 + p];
        m = fmaxf(m, lg[p]);
    }
    float sum = 0.f;
#pragma unroll
    for (int p = 0; p < NP; p++) { lg[p] = expf(lg[p] - m); sum += lg[p]; }
    float rinv = 1.0f / sum;

    const __nv_bfloat16* vbase = g_value_bf + (size_t)b * NV * EE + (size_t)h * HD;
    bool active = (li < 12);

    float acc[8];
#pragma unroll
    for (int k = 0; k < 8; k++) acc[k] = 0.f;

#pragma unroll
    for (int p = 0; p < NP; p++) {
        float lx = rx + raw[h * 8 + p * 2 + 0] * (1.0f / (float)WF);
        float ly = ry + raw[h * 8 + p * 2 + 1] * (1.0f / (float)HF);
        float x = lx * (float)WF - 0.5f;
        float y = ly * (float)HF - 0.5f;
        float a = lg[p] * rinv;
        float fx = floorf(x), fy = floorf(y);
        int x0 = (int)fx, y0 = (int)fy;
        float tx = x - fx, ty = y - fy;
        float w00 = (1.f - tx) * (1.f - ty) * a;
        float w01 = tx * (1.f - ty) * a;
        float w10 = (1.f - tx) * ty * a;
        float w11 = tx * ty * a;
#pragma unroll
        for (int c = 0; c < 4; c++) {
            int xi = x0 + (c & 1);
            int yi = y0 + (c >> 1);
            float w = (c == 0) ? w00 : (c == 1) ? w01 : (c == 2) ? w10 : w11;
            if (active && xi >= 0 && xi < WF && yi >= 0 && yi < HF) {
                const uint4 v = *(const uint4*)(vbase + (size_t)(yi * WF + xi) * EE + li * 8);
                const __nv_bfloat162* pv = (const __nv_bfloat162*)&v;
#pragma unroll
                for (int k = 0; k < 4; k++) {
                    float2 f = __bfloat1622float2(pv[k]);
                    acc[2 * k]     += w * f.x;
                    acc[2 * k + 1] += w * f.y;
                }
            }
        }
    }
    if (active) {
        __nv_bfloat162 p0 = __floats2bfloat162_rn(acc[0], acc[1]);
        __nv_bfloat162 p1 = __floats2bfloat162_rn(acc[2], acc[3]);
        __nv_bfloat162 p2 = __floats2bfloat162_rn(acc[4], acc[5]);
        __nv_bfloat162 p3 = __floats2bfloat162_rn(acc[6], acc[7]);
        uint4 u = make_uint4(*(uint32_t*)&p0, *(uint32_t*)&p1,
                             *(uint32_t*)&p2, *(uint32_t*)&p3);
        *(uint4*)(g_msda_bf + (size_t)bq * EE + (size_t)h * HD + li * 8) = u;
    }
}

// ---------------- launch ----------------
extern "C" void kernel_launch(void* const* d_in, const int* in_sizes, int n_in,
                              void* d_out, int out_size)
{
    (void)in_sizes; (void)n_in; (void)out_size;
    const float* query  = (const float*)d_in[0];
    const float* refp   = (const float*)d_in[1];
    const float* feat   = (const float*)d_in[2];
    const float* ln_q_w = (const float*)d_in[5];
    const float* ln_q_b = (const float*)d_in[6];
    const float* ln_f_w = (const float*)d_in[7];
    const float* ln_f_b = (const float*)d_in[8];
    const float* W_value= (const float*)d_in[9];
    const float* b_value= (const float*)d_in[10];
    const float* W_off  = (const float*)d_in[11];
    const float* b_off  = (const float*)d_in[12];
    const float* W_attn = (const float*)d_in[13];
    const float* b_attn = (const float*)d_in[14];
    const float* W_out  = (const float*)d_in[15];
    const float* b_out  = (const float*)d_in[16];
    const float* gamma  = (const float*)d_in[17];
    float* out = (float*)d_out;

    float* bcat;
    __nv_bfloat16 *qnorm_bf, *fnorm_bf, *wv_bf, *wo_bf, *wcat_bf, *msda_bf;
    cudaGetSymbolAddress((void**)&qnorm_bf, g_qnorm_bf);
    cudaGetSymbolAddress((void**)&fnorm_bf, g_fnorm_bf);
    cudaGetSymbolAddress((void**)&wv_bf,    g_wv_bf);
    cudaGetSymbolAddress((void**)&wo_bf,    g_wo_bf);
    cudaGetSymbolAddress((void**)&wcat_bf,  g_wcat_bf);
    cudaGetSymbolAddress((void**)&bcat,     g_bcat);
    cudaGetSymbolAddress((void**)&msda_bf,  g_msda_bf);

    // dyn smem: 3 stages * (128*40 + 32*136) * 2 bytes = 56832
    const int SMEM = 3 * (128 * 40 * 2 + 32 * 136 * 2);
    cudaFuncSetAttribute(gemm_vc,  cudaFuncAttributeMaxDynamicSharedMemorySize, SMEM);
    cudaFuncSetAttribute(gemm_out, cudaFuncAttributeMaxDynamicSharedMemorySize, SMEM);

    // 1. fused prep: LN(feat) + LN(query) + weight conversion
    prep_kernel<<<BV + BQ + CVTB, 192>>>(query, feat, ln_q_w, ln_q_b, ln_f_w, ln_f_b,
                                         W_value, W_out, W_off, b_off, W_attn, b_attn);

    // 2. merged value + cat GEMM (value tiles overlap cat tiles)
    gemm_vc<<<dim3(EE / 128, BV / 128 + BQ / 128), 128, SMEM>>>(
        fnorm_bf, wv_bf, b_value, qnorm_bf, wcat_bf, bcat);

    // 3. fused softmax + deformable sampling: 1 warp per (b,q, head-pair)
    msda_kernel<<<(BQ * (NH / 2) * 32) / 256, 256>>>(refp);

    // 4. out projection + fused residual: d_out = query + gamma*(qnorm + msda@W_out + b_out)
    gemm_out<<<dim3(EE / 128, BQ / 128), 128, SMEM>>>(
        msda_bf, wo_bf, b_out, out, qnorm_bf, query, gamma);
}

// round 15
// speedup vs baseline: 1.0726x; 1.0020x over previous
#include <cuda_runtime.h>
#include <cuda_bf16.h>
#include <cstdint>
#include <cstddef>

// ---------------- problem constants ----------------
#define BB   4
#define NQ   4096
#define NV   9216
#define EE   768
#define NH   8
#define NP   4
#define HD   96
#define HF   96
#define WF   96

#define BQ   (BB * NQ)   // 16384 query rows
#define BV   (BB * NV)   // 36864 feat rows
#define NCAT 128         // padded N for offset+attn projection
#define CVTB 512         // cvt helper blocks inside prep kernel

// ---------------- scratch (device globals) ----------------
__device__ __nv_bfloat16  g_qnorm_bf[(size_t)BQ * EE];
__device__ __nv_bfloat16  g_fnorm_bf[(size_t)BV * EE];
__device__ __nv_bfloat16  g_value_bf[(size_t)BV * EE];     // value proj (bf16)
__device__ float          g_raw     [(size_t)BQ * NCAT];
__device__ __nv_bfloat16  g_wv_bf   [(size_t)EE * EE];
__device__ __nv_bfloat16  g_wo_bf   [(size_t)EE * EE];
__device__ __nv_bfloat16  g_wcat_bf [(size_t)EE * NCAT];
__device__ float          g_bcat    [NCAT];
__device__ __nv_bfloat16  g_msda_bf [(size_t)BQ * EE];

// ---------------- PTX helpers ----------------
__device__ __forceinline__ void ldsm4(uint32_t& r0, uint32_t& r1, uint32_t& r2, uint32_t& r3,
                                      uint32_t addr)
{
    asm volatile("ldmatrix.sync.aligned.m8n8.x4.shared.b16 {%0,%1,%2,%3}, [%4];"
                 : "=r"(r0), "=r"(r1), "=r"(r2), "=r"(r3) : "r"(addr));
}
__device__ __forceinline__ void ldsm4t(uint32_t& r0, uint32_t& r1, uint32_t& r2, uint32_t& r3,
                                       uint32_t addr)
{
    asm volatile("ldmatrix.sync.aligned.m8n8.x4.trans.shared.b16 {%0,%1,%2,%3}, [%4];"
                 : "=r"(r0), "=r"(r1), "=r"(r2), "=r"(r3) : "r"(addr));
}
__device__ __forceinline__ void mma16816(float* c, uint32_t a0, uint32_t a1, uint32_t a2,
                                         uint32_t a3, uint32_t b0, uint32_t b1)
{
    asm volatile("mma.sync.aligned.m16n8k16.row.col.f32.bf16.bf16.f32 "
                 "{%0,%1,%2,%3}, {%4,%5,%6,%7}, {%8,%9}, {%0,%1,%2,%3};"
                 : "+f"(c[0]), "+f"(c[1]), "+f"(c[2]), "+f"(c[3])
                 : "r"(a0), "r"(a1), "r"(a2), "r"(a3), "r"(b0), "r"(b1));
}
#define CP_ASYNC16(dst, src) \
    asm volatile("cp.async.cg.shared.global [%0], [%1], 16;" :: "r"(dst), "l"(src))
#define CP_COMMIT() asm volatile("cp.async.commit_group;" ::: "memory")
#define CP_WAIT1()  asm volatile("cp.async.wait_group 1;"  ::: "memory")

// ---------------- device fn: row LayerNorm (192 threads) ----------------
__device__ __forceinline__ void ln_row(const float* __restrict__ x,
                                       const float* __restrict__ w,
                                       const float* __restrict__ b,
                                       __nv_bfloat16* __restrict__ yb, int row)
{
    __shared__ float rs[6], rq[6];
    int t = threadIdx.x;                      // 192 threads, 4 floats each
    const float4 v = *(const float4*)(x + (size_t)row * EE + t * 4);
    float s = v.x + v.y + v.z + v.w;
    float q = v.x * v.x + v.y * v.y + v.z * v.z + v.w * v.w;
#pragma unroll
    for (int o = 16; o > 0; o >>= 1) {
        s += __shfl_down_sync(0xffffffffu, s, o);
        q += __shfl_down_sync(0xffffffffu, q, o);
    }
    int wid = t >> 5, lane = t & 31;
    if (lane == 0) { rs[wid] = s; rq[wid] = q; }
    __syncthreads();
    float S = 0.f, Q = 0.f;
#pragma unroll
    for (int i = 0; i < 6; i++) { S += rs[i]; Q += rq[i]; }
    const float inv = 1.0f / (float)EE;
    float mean = S * inv;
    float var  = Q * inv - mean * mean;
    float r    = rsqrtf(var + 1e-6f);
    const float4 wv = *(const float4*)(w + t * 4);
    const float4 bv = *(const float4*)(b + t * 4);
    float o0 = (v.x - mean) * r * wv.x + bv.x;
    float o1 = (v.y - mean) * r * wv.y + bv.y;
    float o2 = (v.z - mean) * r * wv.z + bv.z;
    float o3 = (v.w - mean) * r * wv.w + bv.w;
    __nv_bfloat162 p0 = __floats2bfloat162_rn(o0, o1);
    __nv_bfloat162 p1 = __floats2bfloat162_rn(o2, o3);
    uint2 u = make_uint2(*(uint32_t*)&p0, *(uint32_t*)&p1);
    *(uint2*)&yb[(size_t)row * EE + t * 4] = u;
}

// ---------------- kernel: fused prep = LN(feat) + LN(query) + weight cvt ----------------
// grid: [0,BV) LN(feat); [BV,BV+BQ) LN(query); rest: weight conversion
__global__ void prep_kernel(const float* __restrict__ query, const float* __restrict__ feat,
                            const float* __restrict__ ln_q_w, const float* __restrict__ ln_q_b,
                            const float* __restrict__ ln_f_w, const float* __restrict__ ln_f_b,
                            const float* __restrict__ Wv, const float* __restrict__ Wo,
                            const float* __restrict__ W_off, const float* __restrict__ b_off,
                            const float* __restrict__ W_attn, const float* __restrict__ b_attn)
{
    int blk = blockIdx.x;
    if (blk < BV) {
        ln_row(feat, ln_f_w, ln_f_b, g_fnorm_bf, blk);
        return;
    }
    blk -= BV;
    if (blk < BQ) {
        ln_row(query, ln_q_w, ln_q_b, g_qnorm_bf, blk);
        return;
    }
    // weight conversion blocks
    int cid = blk - BQ;
    const int STR = CVTB * 192;
    for (size_t i = (size_t)cid * 192 + threadIdx.x; i < (size_t)EE * EE; i += STR) {
        g_wv_bf[i] = __float2bfloat16(Wv[i]);
        g_wo_bf[i] = __float2bfloat16(Wo[i]);
    }
    for (size_t i = (size_t)cid * 192 + threadIdx.x; i < (size_t)EE * NCAT; i += STR) {
        int k = (int)(i / NCAT), n = (int)(i % NCAT);
        float v = 0.f;
        if (n < 64)      v = W_off[k * 64 + n];
        else if (n < 96) v = W_attn[k * 32 + (n - 64)];
        g_wcat_bf[i] = __float2bfloat16(v);
    }
    if (cid == 0 && threadIdx.x < NCAT) {
        int idx = threadIdx.x;
        float v = 0.f;
        if (idx < 64)      v = b_off[idx];
        else if (idx < 96) v = b_attn[idx - 64];
        g_bcat[idx] = v;
    }
}

// ---------------- GEMM mainloop body (BK=32, 4 warps, warp tile 64x64) ----------------
// Fragments for BOTH k16 steps loaded up front (16 ldmatrix burst), then 64 MMAs.
struct GemmCfg {
    static constexpr int BM = 128, BN = 128, BK = 32, STAGES = 3;
    static constexpr int MI = 4, NI = 8, NJ2 = 4;
    static constexpr int PA = BK + 8;                 // 40 bf16
    static constexpr int PB = BN + 8;                 // 136 bf16
    static constexpr int ASZ = BM * PA * 2;
    static constexpr int BSZ = BK * PB * 2;
    static constexpr int SB  = ASZ + BSZ;
};

__device__ __forceinline__ void gemm_mainloop(
    const __nv_bfloat16* __restrict__ A, const __nv_bfloat16* __restrict__ Bm,
    int N, int K, int rowBase, int colBase, uint32_t smemU,
    float acc[GemmCfg::MI][GemmCfg::NI][4])
{
    using C = GemmCfg;
    int tid = threadIdx.x, warp = tid >> 5, lane = tid & 31;
    int wm = (warp >> 1) * 64;
    int wn = (warp & 1) * 64;

    int ar = tid >> 2, ac = (tid & 3) * 8;     // A: 32 rows / round, 4 rounds
    int br = tid >> 4, bc = (tid & 15) * 8;    // B: 8 rows / round, 4 rounds
    const __nv_bfloat16* Ag = A  + (size_t)(rowBase + ar) * K + ac;
    const __nv_bfloat16* Bg = Bm + (size_t)br * N + colBase + bc;
    uint32_t aDst = (uint32_t)(ar * C::PA + ac) * 2;
    uint32_t bDst = (uint32_t)(br * C::PB + bc) * 2;

    uint32_t aLd[C::MI], bLd[C::NJ2];
#pragma unroll
    for (int i = 0; i < C::MI; i++)
        aLd[i] = (uint32_t)((wm + i * 16 + (lane & 15)) * C::PA + (lane >> 4) * 8) * 2;
#pragma unroll
    for (int j = 0; j < C::NJ2; j++)
        bLd[j] = (uint32_t)((lane & 15) * C::PB + wn + j * 16 + (lane >> 4) * 8) * 2;

#pragma unroll
    for (int i = 0; i < C::MI; i++)
#pragma unroll
        for (int j = 0; j < C::NI; j++)
#pragma unroll
            for (int v = 0; v < 4; v++) acc[i][j][v] = 0.f;

    const int KT = K / C::BK;

    auto issue = [&](int kt, int s) {
        uint32_t aB = smemU + s * C::SB + aDst;
        uint32_t bB = smemU + s * C::SB + C::ASZ + bDst;
#pragma unroll
        for (int r = 0; r < 4; r++)
            CP_ASYNC16(aB + r * 32 * C::PA * 2, Ag + (size_t)(r * 32) * K + kt);
#pragma unroll
        for (int r = 0; r < 4; r++)
            CP_ASYNC16(bB + r * 8 * C::PB * 2, Bg + (size_t)(kt + r * 8) * N);
        CP_COMMIT();
    };

#pragma unroll
    for (int s = 0; s < C::STAGES - 1; s++) issue(s * C::BK, s);

    for (int t = 0; t < KT; t++) {
        CP_WAIT1();
        __syncthreads();
        int nk = t + C::STAGES - 1;
        if (nk < KT) issue(nk * C::BK, nk % C::STAGES);
        else CP_COMMIT();

        uint32_t aB = smemU + (t % C::STAGES) * C::SB;
        uint32_t bB = aB + C::ASZ;

        // load fragments for BOTH k16 steps up front (LSU-pipelined burst)
        uint32_t af[2][C::MI][4], bf[2][C::NJ2][4];
#pragma unroll
        for (int ks = 0; ks < 2; ks++) {
#pragma unroll
            for (int i = 0; i < C::MI; i++)
                ldsm4(af[ks][i][0], af[ks][i][1], af[ks][i][2], af[ks][i][3],
                      aB + aLd[i] + ks * 32);
#pragma unroll
            for (int j = 0; j < C::NJ2; j++)
                ldsm4t(bf[ks][j][0], bf[ks][j][1], bf[ks][j][2], bf[ks][j][3],
                       bB + bLd[j] + ks * 16 * C::PB * 2);
        }
#pragma unroll
        for (int ks = 0; ks < 2; ks++)
#pragma unroll
            for (int i = 0; i < C::MI; i++)
#pragma unroll
                for (int j = 0; j < C::NI; j++)
                    mma16816(acc[i][j],
                             af[ks][i][0], af[ks][i][1], af[ks][i][2], af[ks][i][3],
                             bf[ks][j >> 1][(j & 1) * 2], bf[ks][j >> 1][(j & 1) * 2 + 1]);
    }
}

// ---------------- kernel: merged value + cat GEMM ----------------
// grid (6, 416): y<288 -> value tiles (bf16 out); y>=288 & x==0 -> cat tiles (f32 out)
__global__ void __launch_bounds__(128, 2)
gemm_vc(const __nv_bfloat16* __restrict__ Av, const __nv_bfloat16* __restrict__ Bv,
        const float* __restrict__ biasv,
        const __nv_bfloat16* __restrict__ Ac, const __nv_bfloat16* __restrict__ Bc,
        const float* __restrict__ biasc)
{
    extern __shared__ char smem[];
    uint32_t smemU = (uint32_t)__cvta_generic_to_shared(smem);

    const __nv_bfloat16 *A, *Bm;
    const float* bias;
    int N, rowBase, colBase, mode;
    if (blockIdx.y < 288) {
        A = Av; Bm = Bv; bias = biasv; N = EE; mode = 1;
        rowBase = blockIdx.y * 128; colBase = blockIdx.x * 128;
    } else {
        if (blockIdx.x != 0) return;
        A = Ac; Bm = Bc; bias = biasc; N = NCAT; mode = 0;
        rowBase = (blockIdx.y - 288) * 128; colBase = 0;
    }

    float acc[GemmCfg::MI][GemmCfg::NI][4];
    gemm_mainloop(A, Bm, N, EE, rowBase, colBase, smemU, acc);

    int lane = threadIdx.x & 31, warp = threadIdx.x >> 5;
    int wm = (warp >> 1) * 64, wn = (warp & 1) * 64;
    int g = lane >> 2, tg = lane & 3;
#pragma unroll
    for (int i = 0; i < GemmCfg::MI; i++) {
#pragma unroll
        for (int j = 0; j < GemmCfg::NI; j++) {
            int row = rowBase + wm + i * 16 + g;
            int col = colBase + wn + j * 8 + tg * 2;
            float b0 = bias[col], b1 = bias[col + 1];
            float v00 = acc[i][j][0] + b0, v01 = acc[i][j][1] + b1;
            float v10 = acc[i][j][2] + b0, v11 = acc[i][j][3] + b1;
            if (mode == 1) {
                *(__nv_bfloat162*)&g_value_bf[(size_t)row * EE + col] =
                    __floats2bfloat162_rn(v00, v01);
                *(__nv_bfloat162*)&g_value_bf[(size_t)(row + 8) * EE + col] =
                    __floats2bfloat162_rn(v10, v11);
            } else {
                *(float2*)&g_raw[(size_t)row * NCAT + col]       = make_float2(v00, v01);
                *(float2*)&g_raw[(size_t)(row + 8) * NCAT + col] = make_float2(v10, v11);
            }
        }
    }
}

// ---------------- kernel: out projection + fused residual ----------------
// fp32 out = qin + gamma*(bf16(qnb) + A@B + bias), N == EE
__global__ void __launch_bounds__(128, 2)
gemm_out(const __nv_bfloat16* __restrict__ A, const __nv_bfloat16* __restrict__ Bm,
         const float* __restrict__ bias, float* __restrict__ Cout,
         const __nv_bfloat16* __restrict__ qnb, const float* __restrict__ qin,
         const float* __restrict__ gamma)
{
    extern __shared__ char smem[];
    uint32_t smemU = (uint32_t)__cvta_generic_to_shared(smem);
    int rowBase = blockIdx.y * 128;
    int colBase = blockIdx.x * 128;

    float acc[GemmCfg::MI][GemmCfg::NI][4];
    gemm_mainloop(A, Bm, EE, EE, rowBase, colBase, smemU, acc);

    int lane = threadIdx.x & 31, warp = threadIdx.x >> 5;
    int wm = (warp >> 1) * 64, wn = (warp & 1) * 64;
    int g = lane >> 2, tg = lane & 3;
#pragma unroll
    for (int i = 0; i < GemmCfg::MI; i++) {
#pragma unroll
        for (int j = 0; j < GemmCfg::NI; j++) {
            int row = rowBase + wm + i * 16 + g;
            int col = colBase + wn + j * 8 + tg * 2;
            float b0 = bias[col], b1 = bias[col + 1];
            float v00 = acc[i][j][0] + b0, v01 = acc[i][j][1] + b1;
            float v10 = acc[i][j][2] + b0, v11 = acc[i][j][3] + b1;
            float gc0 = gamma[col], gc1 = gamma[col + 1];
            size_t o0 = (size_t)row * EE + col;
            size_t o1 = (size_t)(row + 8) * EE + col;
            float2 q0 = *(const float2*)&qin[o0];
            float2 q1 = *(const float2*)&qin[o1];
            __nv_bfloat162 n0 = *(const __nv_bfloat162*)&qnb[o0];
            __nv_bfloat162 n1 = *(const __nv_bfloat162*)&qnb[o1];
            v00 = q0.x + gc0 * (__bfloat162float(n0.x) + v00);
            v01 = q0.y + gc1 * (__bfloat162float(n0.y) + v01);
            v10 = q1.x + gc0 * (__bfloat162float(n1.x) + v10);
            v11 = q1.y + gc1 * (__bfloat162float(n1.y) + v11);
            *(float2*)&Cout[o0] = make_float2(v00, v01);
            *(float2*)&Cout[o1] = make_float2(v10, v11);
        }
    }
}

// ---------------- kernel: fused softmax + deformable bilinear sampling ----------------
__global__ void msda_kernel(const float* __restrict__ refp)
{
    int gwarp = (blockIdx.x * blockDim.x + threadIdx.x) >> 5;
    int lane  = threadIdx.x & 31;
    if (gwarp >= BQ * (NH / 2)) return;
    int bq = gwarp >> 2;                 // / (NH/2)
    int hp = gwarp & 3;
    int h  = hp * 2 + (lane >> 4);
    int li = lane & 15;                  // lane within half-warp; active if li < 12
    int b  = bq >> 12;                   // bq / NQ

    const float* raw = g_raw + (size_t)bq * NCAT;
    float rx = refp[bq * 2 + 0];
    float ry = refp[bq * 2 + 1];

    float lg[NP];
    float m = -1e30f;
#pragma unroll
    for (int p = 0; p < NP; p++) {
        lg[p] = raw[64 + h * 4 + p];
        m = fmaxf(m, lg[p]);
    }
    float sum = 0.f;
#pragma unroll
    for (int p = 0; p < NP; p++) { lg[p] = expf(lg[p] - m); sum += lg[p]; }
    float rinv = 1.0f / sum;

    const __nv_bfloat16* vbase = g_value_bf + (size_t)b * NV * EE + (size_t)h * HD;
    bool active = (li < 12);

    float acc[8];
#pragma unroll
    for (int k = 0; k < 8; k++) acc[k] = 0.f;

#pragma unroll
    for (int p = 0; p < NP; p++) {
        float lx = rx + raw[h * 8 + p * 2 + 0] * (1.0f / (float)WF);
        float ly = ry + raw[h * 8 + p * 2 + 1] * (1.0f / (float)HF);
        float x = lx * (float)WF - 0.5f;
        float y = ly * (float)HF - 0.5f;
        float a = lg[p] * rinv;
        float fx = floorf(x), fy = floorf(y);
        int x0 = (int)fx, y0 = (int)fy;
        float tx = x - fx, ty = y - fy;
        float w00 = (1.f - tx) * (1.f - ty) * a;
        float w01 = tx * (1.f - ty) * a;
        float w10 = (1.f - tx) * ty * a;
        float w11 = tx * ty * a;
#pragma unroll
        for (int c = 0; c < 4; c++) {
            int xi = x0 + (c & 1);
            int yi = y0 + (c >> 1);
            float w = (c == 0) ? w00 : (c == 1) ? w01 : (c == 2) ? w10 : w11;
            if (active && xi >= 0 && xi < WF && yi >= 0 && yi < HF) {
                const uint4 v = *(const uint4*)(vbase + (size_t)(yi * WF + xi) * EE + li * 8);
                const __nv_bfloat162* pv = (const __nv_bfloat162*)&v;
#pragma unroll
                for (int k = 0; k < 4; k++) {
                    float2 f = __bfloat1622float2(pv[k]);
                    acc[2 * k]     += w * f.x;
                    acc[2 * k + 1] += w * f.y;
                }
            }
        }
    }
    if (active) {
        __nv_bfloat162 p0 = __floats2bfloat162_rn(acc[0], acc[1]);
        __nv_bfloat162 p1 = __floats2bfloat162_rn(acc[2], acc[3]);
        __nv_bfloat162 p2 = __floats2bfloat162_rn(acc[4], acc[5]);
        __nv_bfloat162 p3 = __floats2bfloat162_rn(acc[6], acc[7]);
        uint4 u = make_uint4(*(uint32_t*)&p0, *(uint32_t*)&p1,
                             *(uint32_t*)&p2, *(uint32_t*)&p3);
        *(uint4*)(g_msda_bf + (size_t)bq * EE + (size_t)h * HD + li * 8) = u;
    }
}

// ---------------- launch ----------------
extern "C" void kernel_launch(void* const* d_in, const int* in_sizes, int n_in,
                              void* d_out, int out_size)
{
    (void)in_sizes; (void)n_in; (void)out_size;
    const float* query  = (const float*)d_in[0];
    const float* refp   = (const float*)d_in[1];
    const float* feat   = (const float*)d_in[2];
    const float* ln_q_w = (const float*)d_in[5];
    const float* ln_q_b = (const float*)d_in[6];
    const float* ln_f_w = (const float*)d_in[7];
    const float* ln_f_b = (const float*)d_in[8];
    const float* W_value= (const float*)d_in[9];
    const float* b_value= (const float*)d_in[10];
    const float* W_off  = (const float*)d_in[11];
    const float* b_off  = (const float*)d_in[12];
    const float* W_attn = (const float*)d_in[13];
    const float* b_attn = (const float*)d_in[14];
    const float* W_out  = (const float*)d_in[15];
    const float* b_out  = (const float*)d_in[16];
    const float* gamma  = (const float*)d_in[17];
    float* out = (float*)d_out;

    float* bcat;
    __nv_bfloat16 *qnorm_bf, *fnorm_bf, *wv_bf, *wo_bf, *wcat_bf, *msda_bf;
    cudaGetSymbolAddress((void**)&qnorm_bf, g_qnorm_bf);
    cudaGetSymbolAddress((void**)&fnorm_bf, g_fnorm_bf);
    cudaGetSymbolAddress((void**)&wv_bf,    g_wv_bf);
    cudaGetSymbolAddress((void**)&wo_bf,    g_wo_bf);
    cudaGetSymbolAddress((void**)&wcat_bf,  g_wcat_bf);
    cudaGetSymbolAddress((void**)&bcat,     g_bcat);
    cudaGetSymbolAddress((void**)&msda_bf,  g_msda_bf);

    // dyn smem: 3 stages * (128*40 + 32*136) * 2 bytes = 56832
    const int SMEM = 3 * (128 * 40 * 2 + 32 * 136 * 2);
    cudaFuncSetAttribute(gemm_vc,  cudaFuncAttributeMaxDynamicSharedMemorySize, SMEM);
    cudaFuncSetAttribute(gemm_out, cudaFuncAttributeMaxDynamicSharedMemorySize, SMEM);

    // 1. fused prep: LN(feat) + LN(query) + weight conversion
    prep_kernel<<<BV + BQ + CVTB, 192>>>(query, feat, ln_q_w, ln_q_b, ln_f_w, ln_f_b,
                                         W_value, W_out, W_off, b_off, W_attn, b_attn);

    // 2. merged value + cat GEMM (value tiles overlap cat tiles)
    gemm_vc<<<dim3(EE / 128, BV / 128 + BQ / 128), 128, SMEM>>>(
        fnorm_bf, wv_bf, b_value, qnorm_bf, wcat_bf, bcat);

    // 3. fused softmax + deformable sampling: 1 warp per (b,q, head-pair)
    msda_kernel<<<(BQ * (NH / 2) * 32) / 256, 256>>>(refp);

    // 4. out projection + fused residual: d_out = query + gamma*(qnorm + msda@W_out + b_out)
    gemm_out<<<dim3(EE / 128, BQ / 128), 128, SMEM>>>(
        msda_bf, wo_bf, b_out, out, qnorm_bf, query, gamma);
}

// round 17
// speedup vs baseline: 1.1041x; 1.0294x over previous
#include <cuda_runtime.h>
#include <cuda_bf16.h>
#include <cstdint>
#include <cstddef>

// ---------------- problem constants ----------------
#define BB   4
#define NQ   4096
#define NV   9216
#define EE   768
#define NH   8
#define NP   4
#define HD   96
#define HF   96
#define WF   96

#define BQ   (BB * NQ)   // 16384 query rows
#define BV   (BB * NV)   // 36864 feat rows
#define NCAT 128         // padded N for offset+attn projection
#define CVTB 512         // cvt helper blocks inside prep kernel
#define NROWB ((BV + BQ) / 8)   // 6656 LN blocks (8 rows each)

// ---------------- scratch (device globals) ----------------
__device__ __nv_bfloat16  g_qnorm_bf[(size_t)BQ * EE];
__device__ __nv_bfloat16  g_fnorm_bf[(size_t)BV * EE];
__device__ float          g_qbase   [(size_t)BQ * EE];     // query + gamma*qnorm (fp32)
__device__ __nv_bfloat16  g_value_bf[(size_t)BV * EE];     // value proj (bf16)
__device__ float          g_raw     [(size_t)BQ * NCAT];
__device__ __nv_bfloat16  g_wv_bf   [(size_t)EE * EE];
__device__ __nv_bfloat16  g_wo_bf   [(size_t)EE * EE];     // W_out * diag(gamma), bf16
__device__ __nv_bfloat16  g_wcat_bf [(size_t)EE * NCAT];
__device__ float          g_bcat    [NCAT];
__device__ float          g_bout    [EE];                  // gamma * b_out
__device__ __nv_bfloat16  g_msda_bf [(size_t)BQ * EE];

// ---------------- PTX helpers ----------------
__device__ __forceinline__ void ldsm4(uint32_t& r0, uint32_t& r1, uint32_t& r2, uint32_t& r3,
                                      uint32_t addr)
{
    asm volatile("ldmatrix.sync.aligned.m8n8.x4.shared.b16 {%0,%1,%2,%3}, [%4];"
                 : "=r"(r0), "=r"(r1), "=r"(r2), "=r"(r3) : "r"(addr));
}
__device__ __forceinline__ void ldsm4t(uint32_t& r0, uint32_t& r1, uint32_t& r2, uint32_t& r3,
                                       uint32_t addr)
{
    asm volatile("ldmatrix.sync.aligned.m8n8.x4.trans.shared.b16 {%0,%1,%2,%3}, [%4];"
                 : "=r"(r0), "=r"(r1), "=r"(r2), "=r"(r3) : "r"(addr));
}
__device__ __forceinline__ void mma16816(float* c, uint32_t a0, uint32_t a1, uint32_t a2,
                                         uint32_t a3, uint32_t b0, uint32_t b1)
{
    asm volatile("mma.sync.aligned.m16n8k16.row.col.f32.bf16.bf16.f32 "
                 "{%0,%1,%2,%3}, {%4,%5,%6,%7}, {%8,%9}, {%0,%1,%2,%3};"
                 : "+f"(c[0]), "+f"(c[1]), "+f"(c[2]), "+f"(c[3])
                 : "r"(a0), "r"(a1), "r"(a2), "r"(a3), "r"(b0), "r"(b1));
}
#define CP_ASYNC16(dst, src) \
    asm volatile("cp.async.cg.shared.global [%0], [%1], 16;" :: "r"(dst), "l"(src))
#define CP_COMMIT() asm volatile("cp.async.commit_group;" ::: "memory")
#define CP_WAIT1()  asm volatile("cp.async.wait_group 1;"  ::: "memory")

// ---------------- device fn: warp-per-row LayerNorm (MLP=6, shuffle-only) ----------------
// If qbase != nullptr, also writes qbase = x + gamma * ln(x)   (fp32)
__device__ __forceinline__ void ln_warp(const float* __restrict__ x,
                                        const float* __restrict__ w,
                                        const float* __restrict__ b,
                                        __nv_bfloat16* __restrict__ yb,
                                        float* __restrict__ qbase,
                                        const float* __restrict__ gamma,
                                        int row, int lane)
{
    const float4* xr = (const float4*)(x + (size_t)row * EE);
    float4 v[6];
#pragma unroll
    for (int c = 0; c < 6; c++) v[c] = xr[c * 32 + lane];
    float s = 0.f, q = 0.f;
#pragma unroll
    for (int c = 0; c < 6; c++) {
        s += v[c].x + v[c].y + v[c].z + v[c].w;
        q += v[c].x * v[c].x + v[c].y * v[c].y + v[c].z * v[c].z + v[c].w * v[c].w;
    }
#pragma unroll
    for (int o = 16; o > 0; o >>= 1) {
        s += __shfl_xor_sync(0xffffffffu, s, o);
        q += __shfl_xor_sync(0xffffffffu, q, o);
    }
    const float inv = 1.0f / (float)EE;
    float mean = s * inv;
    float var  = q * inv - mean * mean;
    float r    = rsqrtf(var + 1e-6f);
    const float4* w4 = (const float4*)w;
    const float4* b4 = (const float4*)b;
#pragma unroll
    for (int c = 0; c < 6; c++) {
        int idx = c * 32 + lane;
        float4 wv = w4[idx], bv = b4[idx];
        float o0 = (v[c].x - mean) * r * wv.x + bv.x;
        float o1 = (v[c].y - mean) * r * wv.y + bv.y;
        float o2 = (v[c].z - mean) * r * wv.z + bv.z;
        float o3 = (v[c].w - mean) * r * wv.w + bv.w;
        __nv_bfloat162 p0 = __floats2bfloat162_rn(o0, o1);
        __nv_bfloat162 p1 = __floats2bfloat162_rn(o2, o3);
        uint2 u = make_uint2(*(uint32_t*)&p0, *(uint32_t*)&p1);
        *(uint2*)&yb[(size_t)row * EE + idx * 4] = u;
        if (qbase) {
            float4 g = ((const float4*)gamma)[idx];
            float4 qb;
            qb.x = v[c].x + g.x * o0;
            qb.y = v[c].y + g.y * o1;
            qb.z = v[c].z + g.z * o2;
            qb.w = v[c].w + g.w * o3;
            ((float4*)(qbase + (size_t)row * EE))[idx] = qb;
        }
    }
}

// ---------------- kernel: fused prep = LN(feat) + LN(query)+qbase + weight cvt ----------------
// grid: [0, NROWB) warp-per-row LN blocks (8 rows each); rest: weight conversion
__global__ void prep_kernel(const float* __restrict__ query, const float* __restrict__ feat,
                            const float* __restrict__ ln_q_w, const float* __restrict__ ln_q_b,
                            const float* __restrict__ ln_f_w, const float* __restrict__ ln_f_b,
                            const float* __restrict__ Wv, const float* __restrict__ Wo,
                            const float* __restrict__ W_off, const float* __restrict__ b_off,
                            const float* __restrict__ W_attn, const float* __restrict__ b_attn,
                            const float* __restrict__ b_out, const float* __restrict__ gamma)
{
    int blk = blockIdx.x;
    int warp = threadIdx.x >> 5, lane = threadIdx.x & 31;
    if (blk < NROWB) {
        int row = blk * 8 + warp;
        if (row < BV) {
            ln_warp(feat, ln_f_w, ln_f_b, g_fnorm_bf, nullptr, nullptr, row, lane);
        } else {
            ln_warp(query, ln_q_w, ln_q_b, g_qnorm_bf, g_qbase, gamma, row - BV, lane);
        }
        return;
    }
    // weight conversion blocks (256 threads)
    int cid = blk - NROWB;
    int tid = threadIdx.x;
    const int STR = CVTB * 256;
    for (size_t i = (size_t)cid * 256 + tid; i < (size_t)EE * EE; i += STR) {
        g_wv_bf[i] = __float2bfloat16(Wv[i]);
        int n = (int)(i % EE);
        g_wo_bf[i] = __float2bfloat16(Wo[i] * gamma[n]);
    }
    for (size_t i = (size_t)cid * 256 + tid; i < (size_t)EE * NCAT; i += STR) {
        int k = (int)(i / NCAT), n = (int)(i % NCAT);
        float v = 0.f;
        if (n < 64)      v = W_off[k * 64 + n];
        else if (n < 96) v = W_attn[k * 32 + (n - 64)];
        g_wcat_bf[i] = __float2bfloat16(v);
    }
    for (int i = cid * 256 + tid; i < EE; i += STR)
        g_bout[i] = gamma[i] * b_out[i];
    if (cid == 0 && tid < NCAT) {
        int idx = tid;
        float v = 0.f;
        if (idx < 64)      v = b_off[idx];
        else if (idx < 96) v = b_attn[idx - 64];
        g_bcat[idx] = v;
    }
}

// ---------------- GEMM mainloop body (BK=32, 4 warps, warp tile 64x64) ----------------
struct GemmCfg {
    static constexpr int BM = 128, BN = 128, BK = 32, STAGES = 3;
    static constexpr int MI = 4, NI = 8, NJ2 = 4;
    static constexpr int PA = BK + 8;                 // 40 bf16
    static constexpr int PB = BN + 8;                 // 136 bf16
    static constexpr int ASZ = BM * PA * 2;
    static constexpr int BSZ = BK * PB * 2;
    static constexpr int SB  = ASZ + BSZ;
};

__device__ __forceinline__ void gemm_mainloop(
    const __nv_bfloat16* __restrict__ A, const __nv_bfloat16* __restrict__ Bm,
    int N, int K, int rowBase, int colBase, uint32_t smemU,
    float acc[GemmCfg::MI][GemmCfg::NI][4])
{
    using C = GemmCfg;
    int tid = threadIdx.x, warp = tid >> 5, lane = tid & 31;
    int wm = (warp >> 1) * 64;
    int wn = (warp & 1) * 64;

    int ar = tid >> 2, ac = (tid & 3) * 8;     // A: 32 rows / round, 4 rounds
    int br = tid >> 4, bc = (tid & 15) * 8;    // B: 8 rows / round, 4 rounds
    const __nv_bfloat16* Ag = A  + (size_t)(rowBase + ar) * K + ac;
    const __nv_bfloat16* Bg = Bm + (size_t)br * N + colBase + bc;
    uint32_t aDst = (uint32_t)(ar * C::PA + ac) * 2;
    uint32_t bDst = (uint32_t)(br * C::PB + bc) * 2;

    uint32_t aLd[C::MI], bLd[C::NJ2];
#pragma unroll
    for (int i = 0; i < C::MI; i++)
        aLd[i] = (uint32_t)((wm + i * 16 + (lane & 15)) * C::PA + (lane >> 4) * 8) * 2;
#pragma unroll
    for (int j = 0; j < C::NJ2; j++)
        bLd[j] = (uint32_t)((lane & 15) * C::PB + wn + j * 16 + (lane >> 4) * 8) * 2;

#pragma unroll
    for (int i = 0; i < C::MI; i++)
#pragma unroll
        for (int j = 0; j < C::NI; j++)
#pragma unroll
            for (int v = 0; v < 4; v++) acc[i][j][v] = 0.f;

    const int KT = K / C::BK;

    auto issue = [&](int kt, int s) {
        uint32_t aB = smemU + s * C::SB + aDst;
        uint32_t bB = smemU + s * C::SB + C::ASZ + bDst;
#pragma unroll
        for (int r = 0; r < 4; r++)
            CP_ASYNC16(aB + r * 32 * C::PA * 2, Ag + (size_t)(r * 32) * K + kt);
#pragma unroll
        for (int r = 0; r < 4; r++)
            CP_ASYNC16(bB + r * 8 * C::PB * 2, Bg + (size_t)(kt + r * 8) * N);
        CP_COMMIT();
    };

#pragma unroll
    for (int s = 0; s < C::STAGES - 1; s++) issue(s * C::BK, s);

    for (int t = 0; t < KT; t++) {
        CP_WAIT1();
        __syncthreads();
        int nk = t + C::STAGES - 1;
        if (nk < KT) issue(nk * C::BK, nk % C::STAGES);
        else CP_COMMIT();

        uint32_t aB = smemU + (t % C::STAGES) * C::SB;
        uint32_t bB = aB + C::ASZ;

        uint32_t af[2][C::MI][4], bf[2][C::NJ2][4];
#pragma unroll
        for (int ks = 0; ks < 2; ks++) {
#pragma unroll
            for (int i = 0; i < C::MI; i++)
                ldsm4(af[ks][i][0], af[ks][i][1], af[ks][i][2], af[ks][i][3],
                      aB + aLd[i] + ks * 32);
#pragma unroll
            for (int j = 0; j < C::NJ2; j++)
                ldsm4t(bf[ks][j][0], bf[ks][j][1], bf[ks][j][2], bf[ks][j][3],
                       bB + bLd[j] + ks * 16 * C::PB * 2);
        }
#pragma unroll
        for (int ks = 0; ks < 2; ks++)
#pragma unroll
            for (int i = 0; i < C::MI; i++)
#pragma unroll
                for (int j = 0; j < C::NI; j++)
                    mma16816(acc[i][j],
                             af[ks][i][0], af[ks][i][1], af[ks][i][2], af[ks][i][3],
                             bf[ks][j >> 1][(j & 1) * 2], bf[ks][j >> 1][(j & 1) * 2 + 1]);
    }
}

// ---------------- kernel: merged value + cat GEMM ----------------
// grid (6, 416): y<288 -> value tiles (bf16 out); y>=288 & x==0 -> cat tiles (f32 out)
__global__ void __launch_bounds__(128, 2)
gemm_vc(const __nv_bfloat16* __restrict__ Av, const __nv_bfloat16* __restrict__ Bv,
        const float* __restrict__ biasv,
        const __nv_bfloat16* __restrict__ Ac, const __nv_bfloat16* __restrict__ Bc,
        const float* __restrict__ biasc)
{
    extern __shared__ char smem[];
    uint32_t smemU = (uint32_t)__cvta_generic_to_shared(smem);

    const __nv_bfloat16 *A, *Bm;
    const float* bias;
    int N, rowBase, colBase, mode;
    if (blockIdx.y < 288) {
        A = Av; Bm = Bv; bias = biasv; N = EE; mode = 1;
        rowBase = blockIdx.y * 128; colBase = blockIdx.x * 128;
    } else {
        if (blockIdx.x != 0) return;
        A = Ac; Bm = Bc; bias = biasc; N = NCAT; mode = 0;
        rowBase = (blockIdx.y - 288) * 128; colBase = 0;
    }

    float acc[GemmCfg::MI][GemmCfg::NI][4];
    gemm_mainloop(A, Bm, N, EE, rowBase, colBase, smemU, acc);

    int lane = threadIdx.x & 31, warp = threadIdx.x >> 5;
    int wm = (warp >> 1) * 64, wn = (warp & 1) * 64;
    int g = lane >> 2, tg = lane & 3;
#pragma unroll
    for (int i = 0; i < GemmCfg::MI; i++) {
#pragma unroll
        for (int j = 0; j < GemmCfg::NI; j++) {
            int row = rowBase + wm + i * 16 + g;
            int col = colBase + wn + j * 8 + tg * 2;
            float b0 = bias[col], b1 = bias[col + 1];
            float v00 = acc[i][j][0] + b0, v01 = acc[i][j][1] + b1;
            float v10 = acc[i][j][2] + b0, v11 = acc[i][j][3] + b1;
            if (mode == 1) {
                *(__nv_bfloat162*)&g_value_bf[(size_t)row * EE + col] =
                    __floats2bfloat162_rn(v00, v01);
                *(__nv_bfloat162*)&g_value_bf[(size_t)(row + 8) * EE + col] =
                    __floats2bfloat162_rn(v10, v11);
            } else {
                *(float2*)&g_raw[(size_t)row * NCAT + col]       = make_float2(v00, v01);
                *(float2*)&g_raw[(size_t)(row + 8) * NCAT + col] = make_float2(v10, v11);
            }
        }
    }
}

// ---------------- kernel: out projection, gamma pre-folded ----------------
// fp32 out = qbase + A@(W_out*diag(gamma)) + gamma*b_out
__global__ void __launch_bounds__(128, 2)
gemm_out(const __nv_bfloat16* __restrict__ A, const __nv_bfloat16* __restrict__ Bm,
         const float* __restrict__ bias, float* __restrict__ Cout,
         const float* __restrict__ qbase)
{
    extern __shared__ char smem[];
    uint32_t smemU = (uint32_t)__cvta_generic_to_shared(smem);
    int rowBase = blockIdx.y * 128;
    int colBase = blockIdx.x * 128;

    float acc[GemmCfg::MI][GemmCfg::NI][4];
    gemm_mainloop(A, Bm, EE, EE, rowBase, colBase, smemU, acc);

    int lane = threadIdx.x & 31, warp = threadIdx.x >> 5;
    int wm = (warp >> 1) * 64, wn = (warp & 1) * 64;
    int g = lane >> 2, tg = lane & 3;
#pragma unroll
    for (int i = 0; i < GemmCfg::MI; i++) {
#pragma unroll
        for (int j = 0; j < GemmCfg::NI; j++) {
            int row = rowBase + wm + i * 16 + g;
            int col = colBase + wn + j * 8 + tg * 2;
            float b0 = bias[col], b1 = bias[col + 1];
            size_t o0 = (size_t)row * EE + col;
            size_t o1 = (size_t)(row + 8) * EE + col;
            float2 q0 = *(const float2*)&qbase[o0];
            float2 q1 = *(const float2*)&qbase[o1];
            *(float2*)&Cout[o0] = make_float2(q0.x + acc[i][j][0] + b0,
                                              q0.y + acc[i][j][1] + b1);
            *(float2*)&Cout[o1] = make_float2(q1.x + acc[i][j][2] + b0,
                                              q1.y + acc[i][j][3] + b1);
        }
    }
}

// ---------------- kernel: fused softmax + deformable bilinear sampling ----------------
__global__ void msda_kernel(const float* __restrict__ refp)
{
    int gwarp = (blockIdx.x * blockDim.x + threadIdx.x) >> 5;
    int lane  = threadIdx.x & 31;
    if (gwarp >= BQ * (NH / 2)) return;
    int bq = gwarp >> 2;                 // / (NH/2)
    int hp = gwarp & 3;
    int h  = hp * 2 + (lane >> 4);
    int li = lane & 15;                  // lane within half-warp; active if li < 12
    int b  = bq >> 12;                   // bq / NQ

    const float* raw = g_raw + (size_t)bq * NCAT;
    float rx = refp[bq * 2 + 0];
    float ry = refp[bq * 2 + 1];

    float lg[NP];
    float m = -1e30f;
#pragma unroll
    for (int p = 0; p < NP; p++) {
        lg[p] = raw[64 + h * 4 + p];
        m = fmaxf(m, lg[p]);
    }
    float sum = 0.f;
#pragma unroll
    for (int p = 0; p < NP; p++) { lg[p] = expf(lg[p] - m); sum += lg[p]; }
    float rinv = 1.0f / sum;

    const __nv_bfloat16* vbase = g_value_bf + (size_t)b * NV * EE + (size_t)h * HD;
    bool active = (li < 12);

    float acc[8];
#pragma unroll
    for (int k = 0; k < 8; k++) acc[k] = 0.f;

#pragma unroll
    for (int p = 0; p < NP; p++) {
        float lx = rx + raw[h * 8 + p * 2 + 0] * (1.0f / (float)WF);
        float ly = ry + raw[h * 8 + p * 2 + 1] * (1.0f / (float)HF);
        float x = lx * (float)WF - 0.5f;
        float y = ly * (float)HF - 0.5f;
        float a = lg[p] * rinv;
        float fx = floorf(x), fy = floorf(y);
        int x0 = (int)fx, y0 = (int)fy;
        float tx = x - fx, ty = y - fy;
        float w00 = (1.f - tx) * (1.f - ty) * a;
        float w01 = tx * (1.f - ty) * a;
        float w10 = (1.f - tx) * ty * a;
        float w11 = tx * ty * a;
#pragma unroll
        for (int c = 0; c < 4; c++) {
            int xi = x0 + (c & 1);
            int yi = y0 + (c >> 1);
            float w = (c == 0) ? w00 : (c == 1) ? w01 : (c == 2) ? w10 : w11;
            if (active && xi >= 0 && xi < WF && yi >= 0 && yi < HF) {
                const uint4 v = *(const uint4*)(vbase + (size_t)(yi * WF + xi) * EE + li * 8);
                const __nv_bfloat162* pv = (const __nv_bfloat162*)&v;
#pragma unroll
                for (int k = 0; k < 4; k++) {
                    float2 f = __bfloat1622float2(pv[k]);
                    acc[2 * k]     += w * f.x;
                    acc[2 * k + 1] += w * f.y;
                }
            }
        }
    }
    if (active) {
        __nv_bfloat162 p0 = __floats2bfloat162_rn(acc[0], acc[1]);
        __nv_bfloat162 p1 = __floats2bfloat162_rn(acc[2], acc[3]);
        __nv_bfloat162 p2 = __floats2bfloat162_rn(acc[4], acc[5]);
        __nv_bfloat162 p3 = __floats2bfloat162_rn(acc[6], acc[7]);
        uint4 u = make_uint4(*(uint32_t*)&p0, *(uint32_t*)&p1,
                             *(uint32_t*)&p2, *(uint32_t*)&p3);
        *(uint4*)(g_msda_bf + (size_t)bq * EE + (size_t)h * HD + li * 8) = u;
    }
}

// ---------------- launch ----------------
extern "C" void kernel_launch(void* const* d_in, const int* in_sizes, int n_in,
                              void* d_out, int out_size)
{
    (void)in_sizes; (void)n_in; (void)out_size;
    const float* query  = (const float*)d_in[0];
    const float* refp   = (const float*)d_in[1];
    const float* feat   = (const float*)d_in[2];
    const float* ln_q_w = (const float*)d_in[5];
    const float* ln_q_b = (const float*)d_in[6];
    const float* ln_f_w = (const float*)d_in[7];
    const float* ln_f_b = (const float*)d_in[8];
    const float* W_value= (const float*)d_in[9];
    const float* b_value= (const float*)d_in[10];
    const float* W_off  = (const float*)d_in[11];
    const float* b_off  = (const float*)d_in[12];
    const float* W_attn = (const float*)d_in[13];
    const float* b_attn = (const float*)d_in[14];
    const float* W_out  = (const float*)d_in[15];
    const float* b_out  = (const float*)d_in[16];
    const float* gamma  = (const float*)d_in[17];
    float* out = (float*)d_out;

    float *bcat, *bout, *qbase;
    __nv_bfloat16 *qnorm_bf, *fnorm_bf, *wv_bf, *wo_bf, *wcat_bf, *msda_bf;
    cudaGetSymbolAddress((void**)&qnorm_bf, g_qnorm_bf);
    cudaGetSymbolAddress((void**)&fnorm_bf, g_fnorm_bf);
    cudaGetSymbolAddress((void**)&qbase,    g_qbase);
    cudaGetSymbolAddress((void**)&wv_bf,    g_wv_bf);
    cudaGetSymbolAddress((void**)&wo_bf,    g_wo_bf);
    cudaGetSymbolAddress((void**)&wcat_bf,  g_wcat_bf);
    cudaGetSymbolAddress((void**)&bcat,     g_bcat);
    cudaGetSymbolAddress((void**)&bout,     g_bout);
    cudaGetSymbolAddress((void**)&msda_bf,  g_msda_bf);

    // dyn smem: 3 stages * (128*40 + 32*136) * 2 bytes = 56832
    const int SMEM = 3 * (128 * 40 * 2 + 32 * 136 * 2);
    cudaFuncSetAttribute(gemm_vc,  cudaFuncAttributeMaxDynamicSharedMemorySize, SMEM);
    cudaFuncSetAttribute(gemm_out, cudaFuncAttributeMaxDynamicSharedMemorySize, SMEM);

    // 1. fused prep: LN(feat) + LN(query)+qbase + weight conversion (gamma folded)
    prep_kernel<<<NROWB + CVTB, 256>>>(query, feat, ln_q_w, ln_q_b, ln_f_w, ln_f_b,
                                       W_value, W_out, W_off, b_off, W_attn, b_attn,
                                       b_out, gamma);

    // 2. merged value + cat GEMM (value tiles overlap cat tiles)
    gemm_vc<<<dim3(EE / 128, BV / 128 + BQ / 128), 128, SMEM>>>(
        fnorm_bf, wv_bf, b_value, qnorm_bf, wcat_bf, bcat);

    // 3. fused softmax + deformable sampling: 1 warp per (b,q, head-pair)
    msda_kernel<<<(BQ * (NH / 2) * 32) / 256, 256>>>(refp);

    // 4. out projection: d_out = qbase + msda@(W_out*gamma) + gamma*b_out
    gemm_out<<<dim3(EE / 128, BQ / 128), 128, SMEM>>>(
        msda_bf, wo_bf, bout, out, qbase);
}